// round 15
// baseline (speedup 1.0000x reference)
#include <cuda_runtime.h>
#include <cuda_fp16.h>
#include <cstdint>

#define NN 50000
#define DD 128
#define EE 600000
#define CC 40
#define LL 4

// ---------------- scratch (static device globals; no allocation) ----------------
__device__ __align__(16) float g_h  [NN * DD];
__device__ __align__(16) float g_agg[NN * DD];
__device__ __align__(16) float g_gate[NN];
__device__ __align__(16) int   g_rowptr[NN + 4];
__device__ __align__(16) int   g_cursor[NN];
__device__ __align__(16) int   g_srcs[EE + NN];

// ---------------- helpers ----------------
__device__ __forceinline__ unsigned long long ffma2(unsigned long long a,
                                                    unsigned long long b,
                                                    unsigned long long c) {
    unsigned long long d;
    asm("fma.rn.f32x2 %0, %1, %2, %3;" : "=l"(d) : "l"(a), "l"(b), "l"(c));
    return d;
}
__device__ __forceinline__ unsigned long long pack2(float x, float y) {
    unsigned long long r;
    asm("mov.b64 %0, {%1, %2};" : "=l"(r) : "f"(x), "f"(y));
    return r;
}
__device__ __forceinline__ float2 unpack2(unsigned long long v) {
    float2 f;
    asm("mov.b64 {%0, %1}, %2;" : "=f"(f.x), "=f"(f.y) : "l"(v));
    return f;
}
__device__ __forceinline__ float hsw(float x) {
    return x * fminf(fmaxf(x + 3.f, 0.f), 6.f) * (1.f / 6.f);
}
__device__ __forceinline__ uint32_t smem_u32(const void* p) {
    uint32_t a;
    asm("{ .reg .u64 t; cvta.to.shared.u64 t, %1; cvt.u32.u64 %0, t; }" : "=r"(a) : "l"(p));
    return a;
}
// split fp32 pair into fp16x2 hi (returned) and fp16x2 lo residual (out param)
__device__ __forceinline__ uint32_t split_f16(float x0, float x1, uint32_t& lo_pair) {
    __half2 hh = __floats2half2_rn(x0, x1);
    float h0 = __low2float(hh), h1 = __high2float(hh);
    __half2 ll = __floats2half2_rn(x0 - h0, x1 - h1);
    lo_pair = *reinterpret_cast<uint32_t*>(&ll);
    return *reinterpret_cast<uint32_t*>(&hh);
}

#define LDM4(r0, r1, r2, r3, addr) \
    asm volatile("ldmatrix.sync.aligned.m8n8.x4.shared.b16 {%0,%1,%2,%3}, [%4];" \
                 : "=r"(r0), "=r"(r1), "=r"(r2), "=r"(r3) : "r"(addr))

#define MMAF16(d, a0, a1, a2, a3, b0, b1) \
    asm("mma.sync.aligned.m16n8k16.row.col.f32.f16.f16.f32 " \
        "{%0,%1,%2,%3}, {%4,%5,%6,%7}, {%8,%9}, {%0,%1,%2,%3};" \
        : "+f"(d[0]), "+f"(d[1]), "+f"(d[2]), "+f"(d[3]) \
        : "r"(a0), "r"(a1), "r"(a2), "r"(a3), "r"(b0), "r"(b1))

// ---------------- CSR build ----------------
__global__ void count_ext_kernel(const int* __restrict__ dst, int* __restrict__ cursor,
                                 int e, int n) {
    int i = blockIdx.x * blockDim.x + threadIdx.x;
    if (i >= e + n) return;
    int d = (i < e) ? dst[i] : (i - e);
    atomicAdd(&cursor[d], 1);
}

__global__ void scan_kernel(int* __restrict__ cursor, int* __restrict__ rowptr, int n) {
    __shared__ int wsum[32];
    const int lane = threadIdx.x & 31;
    const int wid  = threadIdx.x >> 5;
    int carry = 0;
    for (int base = 0; base < n; base += 4096) {
        int idx = base + threadIdx.x * 4;
        int4 v = make_int4(0, 0, 0, 0);
        if (idx < n) v = *(const int4*)(cursor + idx);
        int t = v.x + v.y + v.z + v.w;
        int x = t;
        #pragma unroll
        for (int o = 1; o < 32; o <<= 1) {
            int y = __shfl_up_sync(0xffffffffu, x, o);
            if (lane >= o) x += y;
        }
        if (lane == 31) wsum[wid] = x;
        __syncthreads();
        if (wid == 0) {
            int s = wsum[lane];
            #pragma unroll
            for (int o = 1; o < 32; o <<= 1) {
                int y = __shfl_up_sync(0xffffffffu, s, o);
                if (lane >= o) s += y;
            }
            wsum[lane] = s;
        }
        __syncthreads();
        int excl = carry + (wid ? wsum[wid - 1] : 0) + x - t;
        if (idx < n) {
            int4 r;
            r.x = excl;
            r.y = excl + v.x;
            r.z = r.y + v.y;
            r.w = r.z + v.z;
            *(int4*)(rowptr + idx) = r;
            *(int4*)(cursor + idx) = r;
        }
        carry += wsum[31];
        __syncthreads();
    }
    if (threadIdx.x == 0) rowptr[n] = carry;
}

// scatter edges into CSR; extra blocks compute layer-0 gate = x.Wg0 + bg0
__global__ void __launch_bounds__(256)
scatter_gate_kernel(const int* __restrict__ src, const int* __restrict__ dst,
                    int* __restrict__ cursor, int* __restrict__ srcs,
                    const float* __restrict__ x, const float* __restrict__ Wg0,
                    const float* __restrict__ bg0, float* __restrict__ gate,
                    int e, int n, int SB) {
    if ((int)blockIdx.x < SB) {
        int i = blockIdx.x * 256 + threadIdx.x;
        if (i >= e + n) return;
        int d, s;
        if (i < e) { d = dst[i]; s = src[i]; }
        else       { d = i - e;  s = i - e;  }
        int p = atomicAdd(&cursor[d], 1);
        srcs[p] = s;
    } else {
        int bid2 = blockIdx.x - SB;
        int row  = bid2 * 8 + (threadIdx.x >> 5);
        int lane = threadIdx.x & 31;
        if (row >= n) return;
        float4 a = ((const float4*)(x + (size_t)row * DD))[lane];
        float4 b = ((const float4*)Wg0)[lane];
        float s  = a.x * b.x + a.y * b.y + a.z * b.z + a.w * b.w;
        #pragma unroll
        for (int o = 16; o; o >>= 1) s += __shfl_xor_sync(0xffffffffu, s, o);
        if (lane == 0) gate[row] = s + bg0[0];
    }
}

// ---------------- single-pass online softmax aggregation (warp per dst) -------
// per 32-edge block: block max, rescale accumulators, per-lane exp once,
// then 4x-unrolled broadcast accumulation. Normalize at the end.
__global__ void __launch_bounds__(256)
edge_agg_kernel(const int* __restrict__ rowptr, const int* __restrict__ srcs,
                const float* __restrict__ g, const float* __restrict__ h,
                float* __restrict__ agg, int n) {
    int gt   = blockIdx.x * blockDim.x + threadIdx.x;
    int w    = gt >> 5;
    int lane = gt & 31;
    if (w >= n) return;
    int beg = rowptr[w];
    int end = rowptr[w + 1];

    float m = -3.4e38f, sl = 0.f;
    float4 acc0 = make_float4(0.f, 0.f, 0.f, 0.f);
    float4 acc1 = make_float4(0.f, 0.f, 0.f, 0.f);

    for (int j0 = beg; j0 < end; j0 += 32) {
        int  j  = j0 + lane;
        bool ok = (j < end);
        int   sj = ok ? srcs[j] : 0;
        float gi = ok ? g[sj] : -3.4e38f;
        float bm = gi;
        #pragma unroll
        for (int o = 16; o; o >>= 1) bm = fmaxf(bm, __shfl_xor_sync(0xffffffffu, bm, o));
        float nm = fmaxf(m, bm);
        float rs = __expf(m - nm);      // 0 on the first block (m = -3.4e38)
        m = nm;
        sl *= rs;
        acc0.x *= rs; acc0.y *= rs; acc0.z *= rs; acc0.w *= rs;
        acc1.x *= rs; acc1.y *= rs; acc1.z *= rs; acc1.w *= rs;
        float ei = ok ? __expf(gi - m) : 0.f;
        sl += ei;

        int cnt = min(32, end - j0);
        int jj = 0;
        for (; jj + 3 < cnt; jj += 4) {
            float w0 = __shfl_sync(0xffffffffu, ei, jj);
            float w1 = __shfl_sync(0xffffffffu, ei, jj + 1);
            float w2 = __shfl_sync(0xffffffffu, ei, jj + 2);
            float w3 = __shfl_sync(0xffffffffu, ei, jj + 3);
            int   s0 = __shfl_sync(0xffffffffu, sj, jj);
            int   s1 = __shfl_sync(0xffffffffu, sj, jj + 1);
            int   s2 = __shfl_sync(0xffffffffu, sj, jj + 2);
            int   s3 = __shfl_sync(0xffffffffu, sj, jj + 3);
            float4 v0 = ((const float4*)(h + (size_t)s0 * DD))[lane];
            float4 v1 = ((const float4*)(h + (size_t)s1 * DD))[lane];
            float4 v2 = ((const float4*)(h + (size_t)s2 * DD))[lane];
            float4 v3 = ((const float4*)(h + (size_t)s3 * DD))[lane];
            acc0.x = fmaf(w0, v0.x, acc0.x); acc1.x = fmaf(w1, v1.x, acc1.x);
            acc0.y = fmaf(w0, v0.y, acc0.y); acc1.y = fmaf(w1, v1.y, acc1.y);
            acc0.z = fmaf(w0, v0.z, acc0.z); acc1.z = fmaf(w1, v1.z, acc1.z);
            acc0.w = fmaf(w0, v0.w, acc0.w); acc1.w = fmaf(w1, v1.w, acc1.w);
            acc0.x = fmaf(w2, v2.x, acc0.x); acc1.x = fmaf(w3, v3.x, acc1.x);
            acc0.y = fmaf(w2, v2.y, acc0.y); acc1.y = fmaf(w3, v3.y, acc1.y);
            acc0.z = fmaf(w2, v2.z, acc0.z); acc1.z = fmaf(w3, v3.z, acc1.z);
            acc0.w = fmaf(w2, v2.w, acc0.w); acc1.w = fmaf(w3, v3.w, acc1.w);
        }
        for (; jj < cnt; jj++) {
            float w0 = __shfl_sync(0xffffffffu, ei, jj);
            int   s0 = __shfl_sync(0xffffffffu, sj, jj);
            float4 v0 = ((const float4*)(h + (size_t)s0 * DD))[lane];
            acc0.x = fmaf(w0, v0.x, acc0.x);
            acc0.y = fmaf(w0, v0.y, acc0.y);
            acc0.z = fmaf(w0, v0.z, acc0.z);
            acc0.w = fmaf(w0, v0.w, acc0.w);
        }
    }
    #pragma unroll
    for (int o = 16; o; o >>= 1) sl += __shfl_xor_sync(0xffffffffu, sl, o);
    float inv = 1.f / sl;
    acc0.x = (acc0.x + acc1.x) * inv;
    acc0.y = (acc0.y + acc1.y) * inv;
    acc0.z = (acc0.z + acc1.z) * inv;
    acc0.w = (acc0.w + acc1.w) * inv;
    ((float4*)(agg + (size_t)w * DD))[lane] = acc0;
}

// =====================================================================
// HMMA fused layer chain (persistent, 1024 threads, 1 block/SM).
// ALGEBRAIC FUSION: Wf = Wt@W1 computed once per block via tensor-core
// prologue; bf = bt@W1 + b1. Then per 128-row tile only TWO stages:
//   S0: z = hsw(BN(A @ Wf + bf))
//   S1: h = hsw(z @ W2 + b2) -> fp32; (!LAST) gate = h . WgN + bgN
// fp16 2-product activations vs fp16-hi weights.
// =====================================================================
#define WB        32768
#define SM_W0     0          /* Wf (computed)  */
#define SM_W1     32768      /* W1 staged (prologue only); gpp after */
#define SM_W2     65536
#define SM_B0     98304      /* hi 32KB | lo 32KB */
#define SM_B1     163840     /* hi 32KB | lo 32KB */
#define SM_CONST  229376     /* 640 floats */
#define CHAIN_SMEM 231936

template <int LAST>
__global__ void __launch_bounds__(1024)
chain2_mma(const float* __restrict__ A,
           const float* __restrict__ Wt,  const float* __restrict__ bt,
           const float* __restrict__ W1,  const float* __restrict__ b1,
           const float* __restrict__ bng, const float* __restrict__ bnb,
           const float* __restrict__ bnm, const float* __restrict__ bnv,
           const float* __restrict__ W2,  const float* __restrict__ b2,
           const float* __restrict__ WgN, const float* __restrict__ bgN,
           float* __restrict__ hout, float* __restrict__ gate, int nrows) {
    extern __shared__ char smem[];
    const uint32_t sb = smem_u32(smem);
    float* cst = (float*)(smem + SM_CONST);   // bf | scale | shift | b2 | wg
    float* gpp = (float*)(smem + SM_W1);      // gate partials (W1 dead post-prologue)
    const int tid  = threadIdx.x;
    const int wid  = tid >> 5;
    const int lane = tid & 31;
    const int mt = wid & 7;          // row block of 16 (128 rows)
    const int nb = wid >> 3;         // col block of 32
    const int g  = lane >> 2, tg = lane & 3;
    const int lq = lane >> 3, lr = lane & 7;

    // ---- stage W1, W2 (fp16 hi, [n][k] swizzled) ----
    {
        __half* s1 = (__half*)(smem + SM_W1);
        __half* s2 = (__half*)(smem + SM_W2);
        for (int i = tid; i < DD * DD; i += 1024) {
            int k = i >> 7, n = i & 127;
            int off = n * 128 + (((k >> 3) ^ (n & 7)) << 3) + (k & 7);
            s1[off] = __float2half(W1[i]);
            s2[off] = __float2half(W2[i]);
        }
    }
    // ---- constants: bf = bt@W1 + b1; BN scale/shift; b2; wg ----
    if (tid < 128) {
        float a = b1[tid];
        for (int k = 0; k < 128; k++) a = fmaf(bt[k], W1[k * 128 + tid], a);
        cst[tid] = a;
        float sv = bng[tid] * rsqrtf(bnv[tid] + 1e-5f);
        cst[128 + tid] = sv;
        cst[256 + tid] = bnb[tid] - bnm[tid] * sv;
        cst[384 + tid] = b2[tid];
        cst[512 + tid] = LAST ? 0.f : WgN[tid];
    }
    const float bgv = LAST ? 0.f : bgN[0];

    // ---- load Wt into B0 as split activations ----
    #pragma unroll
    for (int it = 0; it < 4; it++) {
        int idx = it * 1024 + tid;
        int r = idx >> 5, c4 = idx & 31;
        float4 f = ((const float4*)(Wt + (size_t)r * DD))[c4];
        uint32_t l01, l23;
        uint32_t h01 = split_f16(f.x, f.y, l01);
        uint32_t h23 = split_f16(f.z, f.w, l23);
        uint32_t off = (uint32_t)r * 256
                     + ((uint32_t)((c4 >> 1) ^ (r & 7)) << 4) + (c4 & 1) * 8;
        *(uint2*)(smem + SM_B0 + off)         = make_uint2(h01, h23);
        *(uint2*)(smem + SM_B0 + 32768 + off) = make_uint2(l01, l23);
    }
    __syncthreads();

    const int a_row = mt * 16 + lr + ((lq & 1) << 3);
    const int a_kh  = lq >> 1;
    const int b_row = nb * 32 + lr + ((lq >> 1) << 3);
    const int b_kh  = lq & 1;
    const int r0l   = mt * 16 + g;

    // ---- prologue MMA: Wf = Wt @ W1 ----
    {
        const uint32_t aRowHi = sb + SM_B0 + a_row * 256;
        const uint32_t aRowLo = sb + SM_B0 + 32768 + a_row * 256;
        const uint32_t bRow   = sb + SM_W1 + b_row * 256;
        float acc[4][4];
        #pragma unroll
        for (int i = 0; i < 4; i++) {
            acc[i][0] = 0.f; acc[i][1] = 0.f; acc[i][2] = 0.f; acc[i][3] = 0.f;
        }
        #pragma unroll
        for (int kk = 0; kk < 8; kk++) {
            uint32_t ca = (uint32_t)(((2 * kk + a_kh) ^ lr) << 4);
            uint32_t cb = (uint32_t)(((2 * kk + b_kh) ^ lr) << 4);
            uint32_t ah0, ah1, ah2, ah3, al0, al1, al2, al3;
            LDM4(ah0, ah1, ah2, ah3, aRowHi + ca);
            LDM4(al0, al1, al2, al3, aRowLo + ca);
            uint32_t bh0, bh1, bh2, bh3, bh4, bh5, bh6, bh7;
            LDM4(bh0, bh1, bh2, bh3, bRow + cb);
            LDM4(bh4, bh5, bh6, bh7, bRow + 4096 + cb);
            MMAF16(acc[0], ah0, ah1, ah2, ah3, bh0, bh1);
            MMAF16(acc[1], ah0, ah1, ah2, ah3, bh2, bh3);
            MMAF16(acc[2], ah0, ah1, ah2, ah3, bh4, bh5);
            MMAF16(acc[3], ah0, ah1, ah2, ah3, bh6, bh7);
            MMAF16(acc[0], al0, al1, al2, al3, bh0, bh1);
            MMAF16(acc[1], al0, al1, al2, al3, bh2, bh3);
            MMAF16(acc[2], al0, al1, al2, al3, bh4, bh5);
            MMAF16(acc[3], al0, al1, al2, al3, bh6, bh7);
        }
        __syncthreads();   // all prologue MMAs done (W1 reads complete)
        __half* wf = (__half*)(smem + SM_W0);
        #pragma unroll
        for (int tt = 0; tt < 4; tt++) {
            int c0 = nb * 32 + tt * 8 + 2 * tg, c1 = c0 + 1;
            int k0 = r0l, k1 = r0l + 8;
            wf[c0 * 128 + (((k0 >> 3) ^ (c0 & 7)) << 3) + (k0 & 7)] = __float2half(acc[tt][0]);
            wf[c1 * 128 + (((k0 >> 3) ^ (c1 & 7)) << 3) + (k0 & 7)] = __float2half(acc[tt][1]);
            wf[c0 * 128 + (((k1 >> 3) ^ (c0 & 7)) << 3) + (k1 & 7)] = __float2half(acc[tt][2]);
            wf[c1 * 128 + (((k1 >> 3) ^ (c1 & 7)) << 3) + (k1 & 7)] = __float2half(acc[tt][3]);
        }
    }
    __syncthreads();   // Wf ready; B0 free

    const int ntiles = (nrows + 127) >> 7;
    int t = blockIdx.x;
    if (t < ntiles) {   // initial A tile -> B0
        #pragma unroll
        for (int it = 0; it < 4; it++) {
            int idx = it * 1024 + tid;
            int r = idx >> 5, c4 = idx & 31;
            int grow = t * 128 + r;
            float4 f = make_float4(0.f, 0.f, 0.f, 0.f);
            if (grow < nrows) f = ((const float4*)(A + (size_t)grow * DD))[c4];
            uint32_t l01, l23;
            uint32_t h01 = split_f16(f.x, f.y, l01);
            uint32_t h23 = split_f16(f.z, f.w, l23);
            uint32_t off = (uint32_t)r * 256
                         + ((uint32_t)((c4 >> 1) ^ (r & 7)) << 4) + (c4 & 1) * 8;
            *(uint2*)(smem + SM_B0 + off)         = make_uint2(h01, h23);
            *(uint2*)(smem + SM_B0 + 32768 + off) = make_uint2(l01, l23);
        }
    }
    __syncthreads();

    for (; t < ntiles; t += gridDim.x) {
        // ===== stage S0: z = hsw(BN(A @ Wf + bf)) -> B1 =====
        {
            const uint32_t aRowHi = sb + SM_B0 + a_row * 256;
            const uint32_t aRowLo = sb + SM_B0 + 32768 + a_row * 256;
            const uint32_t bRow   = sb + SM_W0 + b_row * 256;
            float acc[4][4];
            #pragma unroll
            for (int i = 0; i < 4; i++) {
                acc[i][0] = 0.f; acc[i][1] = 0.f; acc[i][2] = 0.f; acc[i][3] = 0.f;
            }
            #pragma unroll
            for (int kk = 0; kk < 8; kk++) {
                uint32_t ca = (uint32_t)(((2 * kk + a_kh) ^ lr) << 4);
                uint32_t cb = (uint32_t)(((2 * kk + b_kh) ^ lr) << 4);
                uint32_t ah0, ah1, ah2, ah3, al0, al1, al2, al3;
                LDM4(ah0, ah1, ah2, ah3, aRowHi + ca);
                LDM4(al0, al1, al2, al3, aRowLo + ca);
                uint32_t bh0, bh1, bh2, bh3, bh4, bh5, bh6, bh7;
                LDM4(bh0, bh1, bh2, bh3, bRow + cb);
                LDM4(bh4, bh5, bh6, bh7, bRow + 4096 + cb);
                MMAF16(acc[0], ah0, ah1, ah2, ah3, bh0, bh1);
                MMAF16(acc[1], ah0, ah1, ah2, ah3, bh2, bh3);
                MMAF16(acc[2], ah0, ah1, ah2, ah3, bh4, bh5);
                MMAF16(acc[3], ah0, ah1, ah2, ah3, bh6, bh7);
                MMAF16(acc[0], al0, al1, al2, al3, bh0, bh1);
                MMAF16(acc[1], al0, al1, al2, al3, bh2, bh3);
                MMAF16(acc[2], al0, al1, al2, al3, bh4, bh5);
                MMAF16(acc[3], al0, al1, al2, al3, bh6, bh7);
            }
            #pragma unroll
            for (int tt = 0; tt < 4; tt++) {
                int ct = nb * 32 + tt * 8;
                int c0 = ct + 2 * tg, c1 = c0 + 1;
                float v0 = hsw((acc[tt][0] + cst[c0]) * cst[128 + c0] + cst[256 + c0]);
                float v1 = hsw((acc[tt][1] + cst[c1]) * cst[128 + c1] + cst[256 + c1]);
                float v2 = hsw((acc[tt][2] + cst[c0]) * cst[128 + c0] + cst[256 + c0]);
                float v3 = hsw((acc[tt][3] + cst[c1]) * cst[128 + c1] + cst[256 + c1]);
                uint32_t lo01, lo23;
                uint32_t h01 = split_f16(v0, v1, lo01);
                uint32_t h23 = split_f16(v2, v3, lo23);
                uint32_t chunk = (uint32_t)(((ct >> 3) ^ (r0l & 7)) << 4) + 4 * tg;
                uint32_t off0 = (uint32_t)r0l * 256 + chunk;
                uint32_t off1 = (uint32_t)(r0l + 8) * 256 + chunk;
                *(uint32_t*)(smem + SM_B1 + off0)         = h01;
                *(uint32_t*)(smem + SM_B1 + off1)         = h23;
                *(uint32_t*)(smem + SM_B1 + 32768 + off0) = lo01;
                *(uint32_t*)(smem + SM_B1 + 32768 + off1) = lo23;
            }
        }
        __syncthreads();   // (b) B1 published; B0 fully dead

        // ===== stage S1: h = hsw(z @ W2 + b2); prefetch next A into B0 =====
        {
            const int tn = t + gridDim.x;
            float4 pf[4];
            if (tn < ntiles) {
                #pragma unroll
                for (int it = 0; it < 4; it++) {
                    int idx = it * 1024 + tid;
                    int r = idx >> 5, c4 = idx & 31;
                    int grow = tn * 128 + r;
                    pf[it] = (grow < nrows) ? ((const float4*)(A + (size_t)grow * DD))[c4]
                                            : make_float4(0.f, 0.f, 0.f, 0.f);
                }
            }
            const uint32_t aRowHi = sb + SM_B1 + a_row * 256;
            const uint32_t aRowLo = sb + SM_B1 + 32768 + a_row * 256;
            const uint32_t bRow   = sb + SM_W2 + b_row * 256;
            float acc[4][4];
            #pragma unroll
            for (int i = 0; i < 4; i++) {
                acc[i][0] = 0.f; acc[i][1] = 0.f; acc[i][2] = 0.f; acc[i][3] = 0.f;
            }
            #pragma unroll
            for (int kk = 0; kk < 8; kk++) {
                uint32_t ca = (uint32_t)(((2 * kk + a_kh) ^ lr) << 4);
                uint32_t cb = (uint32_t)(((2 * kk + b_kh) ^ lr) << 4);
                uint32_t ah0, ah1, ah2, ah3, al0, al1, al2, al3;
                LDM4(ah0, ah1, ah2, ah3, aRowHi + ca);
                LDM4(al0, al1, al2, al3, aRowLo + ca);
                uint32_t bh0, bh1, bh2, bh3, bh4, bh5, bh6, bh7;
                LDM4(bh0, bh1, bh2, bh3, bRow + cb);
                LDM4(bh4, bh5, bh6, bh7, bRow + 4096 + cb);
                MMAF16(acc[0], ah0, ah1, ah2, ah3, bh0, bh1);
                MMAF16(acc[1], ah0, ah1, ah2, ah3, bh2, bh3);
                MMAF16(acc[2], ah0, ah1, ah2, ah3, bh4, bh5);
                MMAF16(acc[3], ah0, ah1, ah2, ah3, bh6, bh7);
                MMAF16(acc[0], al0, al1, al2, al3, bh0, bh1);
                MMAF16(acc[1], al0, al1, al2, al3, bh2, bh3);
                MMAF16(acc[2], al0, al1, al2, al3, bh4, bh5);
                MMAF16(acc[3], al0, al1, al2, al3, bh6, bh7);
            }
            if (tn < ntiles) {   // store prefetched A into B0 (dead since sync b)
                #pragma unroll
                for (int it = 0; it < 4; it++) {
                    int idx = it * 1024 + tid;
                    int r = idx >> 5, c4 = idx & 31;
                    float4 f = pf[it];
                    uint32_t l01, l23;
                    uint32_t h01 = split_f16(f.x, f.y, l01);
                    uint32_t h23 = split_f16(f.z, f.w, l23);
                    uint32_t off = (uint32_t)r * 256
                                 + ((uint32_t)((c4 >> 1) ^ (r & 7)) << 4) + (c4 & 1) * 8;
                    *(uint2*)(smem + SM_B0 + off)         = make_uint2(h01, h23);
                    *(uint2*)(smem + SM_B0 + 32768 + off) = make_uint2(l01, l23);
                }
            }
            int gr0 = t * 128 + r0l, gr1 = gr0 + 8;
            float p0 = 0.f, p1 = 0.f;
            #pragma unroll
            for (int tt = 0; tt < 4; tt++) {
                int ct = nb * 32 + tt * 8;
                int c0 = ct + 2 * tg, c1 = c0 + 1;
                float q0 = hsw(acc[tt][0] + cst[384 + c0]);
                float q1 = hsw(acc[tt][1] + cst[384 + c1]);
                float q2 = hsw(acc[tt][2] + cst[384 + c0]);
                float q3 = hsw(acc[tt][3] + cst[384 + c1]);
                if (!LAST) {
                    p0 = fmaf(q0, cst[512 + c0], fmaf(q1, cst[512 + c1], p0));
                    p1 = fmaf(q2, cst[512 + c0], fmaf(q3, cst[512 + c1], p1));
                }
                if (gr0 < nrows)
                    *(float2*)(hout + (size_t)gr0 * DD + c0) = make_float2(q0, q1);
                if (gr1 < nrows)
                    *(float2*)(hout + (size_t)gr1 * DD + c0) = make_float2(q2, q3);
            }
            if (!LAST) {
                p0 += __shfl_xor_sync(0xffffffffu, p0, 1);
                p0 += __shfl_xor_sync(0xffffffffu, p0, 2);
                p1 += __shfl_xor_sync(0xffffffffu, p1, 1);
                p1 += __shfl_xor_sync(0xffffffffu, p1, 2);
                if (tg == 0) {
                    gpp[r0l * 4 + nb]       = p0;
                    gpp[(r0l + 8) * 4 + nb] = p1;
                }
            }
        }
        __syncthreads();   // (c) B1 reads done; B0 next-A + gpp published

        if (!LAST) {
            if (tid < 128) {
                int gr = t * 128 + tid;
                if (gr < nrows)
                    gate[gr] = gpp[tid * 4] + gpp[tid * 4 + 1]
                             + gpp[tid * 4 + 2] + gpp[tid * 4 + 3] + bgv;
            }
        }
    }
}

// =====================================================================
// Head (HMMA): z = hsw(h@Wp1+bp1) via fp16 2-product MMA (h fp32 input);
// logits = z@Wp2+bp2 (packed FFMA2); log_softmax. 512 thr, 128-row tiles.
// =====================================================================
#define HD_WP1  0        /* 32768 */
#define HD_AHI  32768    /* 32768 */
#define HD_ALO  65536    /* 32768 */
#define HD_Z    98304    /* 128*132*4 = 67584 */
#define HD_WSH  165888   /* 20480 */
#define HEAD_SMEM 186368

__global__ void __launch_bounds__(512)
head_hmma(const float* __restrict__ h, const float* __restrict__ Wp1,
          const float* __restrict__ bp1, const float* __restrict__ Wp2,
          const float* __restrict__ bp2, float* __restrict__ out, int n) {
    extern __shared__ char smem[];
    const uint32_t sb = smem_u32(smem);
    float* zf = (float*)(smem + HD_Z);
    unsigned long long* wsh = (unsigned long long*)(smem + HD_WSH);
    const int tid  = threadIdx.x;
    const int wid  = tid >> 5;
    const int lane = tid & 31;
    const int mt = wid & 7;
    const int nb = wid >> 3;
    const int g  = lane >> 2, tg = lane & 3;
    const int lq = lane >> 3, lr = lane & 7;
    const int r0 = blockIdx.x * 128;

    {
        __half* hs = (__half*)(smem + HD_WP1);
        for (int i = tid; i < DD * DD; i += 512) {
            int k = i >> 7, nn = i & 127;
            int off = nn * 128 + (((k >> 3) ^ (nn & 7)) << 3) + (k & 7);
            hs[off] = __float2half(Wp1[i]);
        }
    }
    for (int idx = tid; idx < DD * 20; idx += 512) {
        int k = idx / 20, j = idx % 20;
        wsh[idx] = pack2(Wp2[k * CC + 2 * j], Wp2[k * CC + 2 * j + 1]);
    }
    #pragma unroll
    for (int it = 0; it < 8; it++) {
        int idx = it * 512 + tid;
        int r = idx >> 5, c4 = idx & 31;
        int grow = r0 + r;
        float4 f = make_float4(0.f, 0.f, 0.f, 0.f);
        if (grow < n) f = ((const float4*)(h + (size_t)grow * DD))[c4];
        uint32_t l01, l23;
        uint32_t h01 = split_f16(f.x, f.y, l01);
        uint32_t h23 = split_f16(f.z, f.w, l23);
        uint32_t off = (uint32_t)r * 256
                     + ((uint32_t)((c4 >> 1) ^ (r & 7)) << 4) + (c4 & 1) * 8;
        *(uint2*)(smem + HD_AHI + off) = make_uint2(h01, h23);
        *(uint2*)(smem + HD_ALO + off) = make_uint2(l01, l23);
    }
    __syncthreads();

    const int a_row = mt * 16 + lr + ((lq & 1) << 3);
    const int a_kh  = lq >> 1;
    const int b_kh  = lq & 1;
    const uint32_t aRowHi = sb + HD_AHI + a_row * 256;
    const uint32_t aRowLo = sb + HD_ALO + a_row * 256;
    const int brb0 = (nb * 2 + 0) * 32 + lr + ((lq >> 1) << 3);
    const int brb1 = (nb * 2 + 1) * 32 + lr + ((lq >> 1) << 3);
    const uint32_t bRow0 = sb + HD_WP1 + brb0 * 256;
    const uint32_t bRow1 = sb + HD_WP1 + brb1 * 256;
    const int r0l = mt * 16 + g;

    float acc[2][4][4];
    #pragma unroll
    for (int h2 = 0; h2 < 2; h2++)
        #pragma unroll
        for (int i = 0; i < 4; i++) {
            acc[h2][i][0] = 0.f; acc[h2][i][1] = 0.f;
            acc[h2][i][2] = 0.f; acc[h2][i][3] = 0.f;
        }
    #pragma unroll
    for (int kk = 0; kk < 8; kk++) {
        uint32_t ca = (uint32_t)(((2 * kk + a_kh) ^ lr) << 4);
        uint32_t cb = (uint32_t)(((2 * kk + b_kh) ^ lr) << 4);
        uint32_t ah0, ah1, ah2, ah3, al0, al1, al2, al3;
        LDM4(ah0, ah1, ah2, ah3, aRowHi + ca);
        LDM4(al0, al1, al2, al3, aRowLo + ca);
        uint32_t b00, b01, b02, b03, b04, b05, b06, b07;
        LDM4(b00, b01, b02, b03, bRow0 + cb);
        LDM4(b04, b05, b06, b07, bRow0 + 4096 + cb);
        MMAF16(acc[0][0], ah0, ah1, ah2, ah3, b00, b01);
        MMAF16(acc[0][1], ah0, ah1, ah2, ah3, b02, b03);
        MMAF16(acc[0][2], ah0, ah1, ah2, ah3, b04, b05);
        MMAF16(acc[0][3], ah0, ah1, ah2, ah3, b06, b07);
        MMAF16(acc[0][0], al0, al1, al2, al3, b00, b01);
        MMAF16(acc[0][1], al0, al1, al2, al3, b02, b03);
        MMAF16(acc[0][2], al0, al1, al2, al3, b04, b05);
        MMAF16(acc[0][3], al0, al1, al2, al3, b06, b07);
        uint32_t b10, b11, b12, b13, b14, b15, b16, b17;
        LDM4(b10, b11, b12, b13, bRow1 + cb);
        LDM4(b14, b15, b16, b17, bRow1 + 4096 + cb);
        MMAF16(acc[1][0], ah0, ah1, ah2, ah3, b10, b11);
        MMAF16(acc[1][1], ah0, ah1, ah2, ah3, b12, b13);
        MMAF16(acc[1][2], ah0, ah1, ah2, ah3, b14, b15);
        MMAF16(acc[1][3], ah0, ah1, ah2, ah3, b16, b17);
        MMAF16(acc[1][0], al0, al1, al2, al3, b10, b11);
        MMAF16(acc[1][1], al0, al1, al2, al3, b12, b13);
        MMAF16(acc[1][2], al0, al1, al2, al3, b14, b15);
        MMAF16(acc[1][3], al0, al1, al2, al3, b16, b17);
    }
    #pragma unroll
    for (int h2 = 0; h2 < 2; h2++) {
        #pragma unroll
        for (int tt = 0; tt < 4; tt++) {
            int c0 = (nb * 2 + h2) * 32 + tt * 8 + 2 * tg;
            float bb0 = bp1[c0], bb1 = bp1[c0 + 1];
            float q0 = hsw(acc[h2][tt][0] + bb0);
            float q1 = hsw(acc[h2][tt][1] + bb1);
            float q2 = hsw(acc[h2][tt][2] + bb0);
            float q3 = hsw(acc[h2][tt][3] + bb1);
            *(float2*)(zf + r0l * 132 + c0)       = make_float2(q0, q1);
            *(float2*)(zf + (r0l + 8) * 132 + c0) = make_float2(q2, q3);
        }
    }
    __syncthreads();

    const int rl = tid >> 2;
    const int q  = tid & 3;
    unsigned long long acc2[5];
    #pragma unroll
    for (int j = 0; j < 5; j++)
        acc2[j] = pack2(bp2[q * 10 + 2 * j], bp2[q * 10 + 2 * j + 1]);
    const float* ar = zf + rl * 132;
    #pragma unroll 4
    for (int k = 0; k < DD; k++) {
        float a = ar[k];
        unsigned long long ad = pack2(a, a);
        const unsigned long long* wr = wsh + k * 20 + q * 5;
        #pragma unroll
        for (int j = 0; j < 5; j++) acc2[j] = ffma2(ad, wr[j], acc2[j]);
    }
    float vals[10];
    #pragma unroll
    for (int j = 0; j < 5; j++) {
        float2 p = unpack2(acc2[j]);
        vals[2 * j] = p.x;
        vals[2 * j + 1] = p.y;
    }
    float mx = vals[0];
    #pragma unroll
    for (int c = 1; c < 10; c++) mx = fmaxf(mx, vals[c]);
    mx = fmaxf(mx, __shfl_xor_sync(0xffffffffu, mx, 1));
    mx = fmaxf(mx, __shfl_xor_sync(0xffffffffu, mx, 2));
    float s = 0.f;
    #pragma unroll
    for (int c = 0; c < 10; c++) s += __expf(vals[c] - mx);
    s += __shfl_xor_sync(0xffffffffu, s, 1);
    s += __shfl_xor_sync(0xffffffffu, s, 2);
    float lse = mx + logf(s);
    int gr = r0 + rl;
    if (gr < n) {
        #pragma unroll
        for (int c = 0; c < 10; c++) out[(size_t)gr * CC + q * 10 + c] = vals[c] - lse;
    }
}

// ---------------- launch orchestration ----------------
extern "C" void kernel_launch(void* const* d_in, const int* in_sizes, int n_in,
                              void* d_out, int out_size) {
    const float* x   = (const float*)d_in[0];
    const int*   src = (const int*)d_in[1];
    const int*   dst = (const int*)d_in[2];
    const float* Wg  = (const float*)d_in[3];
    const float* bg  = (const float*)d_in[4];
    const float* Wt  = (const float*)d_in[5];
    const float* bt  = (const float*)d_in[6];
    const float* W1  = (const float*)d_in[7];
    const float* b1  = (const float*)d_in[8];
    const float* bng = (const float*)d_in[9];
    const float* bnb = (const float*)d_in[10];
    const float* bnm = (const float*)d_in[11];
    const float* bnv = (const float*)d_in[12];
    const float* W2  = (const float*)d_in[13];
    const float* b2  = (const float*)d_in[14];
    const float* Wp1 = (const float*)d_in[15];
    const float* bp1 = (const float*)d_in[16];
    const float* Wp2 = (const float*)d_in[17];
    const float* bp2 = (const float*)d_in[18];
    float* out = (float*)d_out;

    const int n = in_sizes[0] / DD;
    const int e = in_sizes[1];

    float *ph, *pagg, *pg;
    int *prow, *pcur, *psrc;
    cudaGetSymbolAddress((void**)&ph,   g_h);
    cudaGetSymbolAddress((void**)&pagg, g_agg);
    cudaGetSymbolAddress((void**)&pg,   g_gate);
    cudaGetSymbolAddress((void**)&prow, g_rowptr);
    cudaGetSymbolAddress((void**)&pcur, g_cursor);
    cudaGetSymbolAddress((void**)&psrc, g_srcs);

    cudaFuncSetAttribute(chain2_mma<0>, cudaFuncAttributeMaxDynamicSharedMemorySize, CHAIN_SMEM);
    cudaFuncSetAttribute(chain2_mma<1>, cudaFuncAttributeMaxDynamicSharedMemorySize, CHAIN_SMEM);
    cudaFuncSetAttribute(head_hmma, cudaFuncAttributeMaxDynamicSharedMemorySize, HEAD_SMEM);

    // CSR build + layer-0 gate
    cudaMemsetAsync(pcur, 0, n * sizeof(int));
    count_ext_kernel<<<(e + n + 255) / 256, 256>>>(dst, pcur, e, n);
    scan_kernel<<<1, 1024>>>(pcur, prow, n);
    const int SB = (e + n + 255) / 256;
    const int GB = (n + 7) / 8;
    scatter_gate_kernel<<<SB + GB, 256>>>(src, dst, pcur, psrc,
                                          x, Wg, bg, pg, e, n, SB);

    const int wblocks = (n * 32 + 255) / 256;
    const int PERS = 148;

    for (int i = 0; i < LL; i++) {
        const float* hin = (i == 0) ? x : ph;
        edge_agg_kernel<<<wblocks, 256>>>(prow, psrc, pg, hin, pagg, n);
        if (i < LL - 1) {
            chain2_mma<0><<<PERS, 1024, CHAIN_SMEM>>>(
                pagg,
                Wt + (size_t)i * DD * DD, bt + (size_t)i * DD,
                W1 + (size_t)i * DD * DD, b1 + (size_t)i * DD,
                bng + (size_t)i * DD, bnb + (size_t)i * DD,
                bnm + (size_t)i * DD, bnv + (size_t)i * DD,
                W2 + (size_t)i * DD * DD, b2 + (size_t)i * DD,
                Wg + (size_t)(i + 1) * DD, bg + (i + 1),
                ph, pg, n);
        } else {
            chain2_mma<1><<<PERS, 1024, CHAIN_SMEM>>>(
                pagg,
                Wt + (size_t)i * DD * DD, bt + (size_t)i * DD,
                W1 + (size_t)i * DD * DD, b1 + (size_t)i * DD,
                bng + (size_t)i * DD, bnb + (size_t)i * DD,
                bnm + (size_t)i * DD, bnv + (size_t)i * DD,
                W2 + (size_t)i * DD * DD, b2 + (size_t)i * DD,
                nullptr, nullptr,
                ph, nullptr, n);
        }
    }
    head_hmma<<<(n + 127) / 128, 512, HEAD_SMEM>>>(ph, Wp1, bp1, Wp2, bp2, out, n);
}

// round 17
// speedup vs baseline: 1.0471x; 1.0471x over previous
#include <cuda_runtime.h>
#include <cuda_fp16.h>
#include <cstdint>

#define NN 50000
#define DD 128
#define EE 600000
#define CC 40
#define LL 4

// ---------------- scratch (static device globals; no allocation) ----------------
__device__ __align__(16) float g_h  [NN * DD];
__device__ __align__(16) float g_agg[NN * DD];
__device__ __align__(16) float g_gate[NN];
__device__ __align__(16) int   g_rowptr[NN + 4];
__device__ __align__(16) int   g_cursor[NN];
__device__ __align__(16) int   g_srcs[EE + NN];

// ---------------- helpers ----------------
__device__ __forceinline__ unsigned long long ffma2(unsigned long long a,
                                                    unsigned long long b,
                                                    unsigned long long c) {
    unsigned long long d;
    asm("fma.rn.f32x2 %0, %1, %2, %3;" : "=l"(d) : "l"(a), "l"(b), "l"(c));
    return d;
}
__device__ __forceinline__ unsigned long long pack2(float x, float y) {
    unsigned long long r;
    asm("mov.b64 %0, {%1, %2};" : "=l"(r) : "f"(x), "f"(y));
    return r;
}
__device__ __forceinline__ float2 unpack2(unsigned long long v) {
    float2 f;
    asm("mov.b64 {%0, %1}, %2;" : "=f"(f.x), "=f"(f.y) : "l"(v));
    return f;
}
__device__ __forceinline__ float hsw(float x) {
    return x * fminf(fmaxf(x + 3.f, 0.f), 6.f) * (1.f / 6.f);
}
__device__ __forceinline__ uint32_t smem_u32(const void* p) {
    uint32_t a;
    asm("{ .reg .u64 t; cvta.to.shared.u64 t, %1; cvt.u32.u64 %0, t; }" : "=r"(a) : "l"(p));
    return a;
}
// split fp32 pair into fp16x2 hi (returned) and fp16x2 lo residual (out param)
__device__ __forceinline__ uint32_t split_f16(float x0, float x1, uint32_t& lo_pair) {
    __half2 hh = __floats2half2_rn(x0, x1);
    float h0 = __low2float(hh), h1 = __high2float(hh);
    __half2 ll = __floats2half2_rn(x0 - h0, x1 - h1);
    lo_pair = *reinterpret_cast<uint32_t*>(&ll);
    return *reinterpret_cast<uint32_t*>(&hh);
}

#define LDM4(r0, r1, r2, r3, addr) \
    asm volatile("ldmatrix.sync.aligned.m8n8.x4.shared.b16 {%0,%1,%2,%3}, [%4];" \
                 : "=r"(r0), "=r"(r1), "=r"(r2), "=r"(r3) : "r"(addr))

#define MMAF16(d, a0, a1, a2, a3, b0, b1) \
    asm("mma.sync.aligned.m16n8k16.row.col.f32.f16.f16.f32 " \
        "{%0,%1,%2,%3}, {%4,%5,%6,%7}, {%8,%9}, {%0,%1,%2,%3};" \
        : "+f"(d[0]), "+f"(d[1]), "+f"(d[2]), "+f"(d[3]) \
        : "r"(a0), "r"(a1), "r"(a2), "r"(a3), "r"(b0), "r"(b1))

// ---------------- CSR build ----------------
__global__ void count_ext_kernel(const int* __restrict__ dst, int* __restrict__ cursor,
                                 int e, int n) {
    int i = blockIdx.x * blockDim.x + threadIdx.x;
    if (i >= e + n) return;
    int d = (i < e) ? dst[i] : (i - e);
    atomicAdd(&cursor[d], 1);
}

__global__ void scan_kernel(int* __restrict__ cursor, int* __restrict__ rowptr, int n) {
    __shared__ int wsum[32];
    const int lane = threadIdx.x & 31;
    const int wid  = threadIdx.x >> 5;
    int carry = 0;
    for (int base = 0; base < n; base += 4096) {
        int idx = base + threadIdx.x * 4;
        int4 v = make_int4(0, 0, 0, 0);
        if (idx < n) v = *(const int4*)(cursor + idx);
        int t = v.x + v.y + v.z + v.w;
        int x = t;
        #pragma unroll
        for (int o = 1; o < 32; o <<= 1) {
            int y = __shfl_up_sync(0xffffffffu, x, o);
            if (lane >= o) x += y;
        }
        if (lane == 31) wsum[wid] = x;
        __syncthreads();
        if (wid == 0) {
            int s = wsum[lane];
            #pragma unroll
            for (int o = 1; o < 32; o <<= 1) {
                int y = __shfl_up_sync(0xffffffffu, s, o);
                if (lane >= o) s += y;
            }
            wsum[lane] = s;
        }
        __syncthreads();
        int excl = carry + (wid ? wsum[wid - 1] : 0) + x - t;
        if (idx < n) {
            int4 r;
            r.x = excl;
            r.y = excl + v.x;
            r.z = r.y + v.y;
            r.w = r.z + v.z;
            *(int4*)(rowptr + idx) = r;
            *(int4*)(cursor + idx) = r;
        }
        carry += wsum[31];
        __syncthreads();
    }
    if (threadIdx.x == 0) rowptr[n] = carry;
}

// scatter edges into CSR; extra blocks compute layer-0 gate = x.Wg0 + bg0
__global__ void __launch_bounds__(256)
scatter_gate_kernel(const int* __restrict__ src, const int* __restrict__ dst,
                    int* __restrict__ cursor, int* __restrict__ srcs,
                    const float* __restrict__ x, const float* __restrict__ Wg0,
                    const float* __restrict__ bg0, float* __restrict__ gate,
                    int e, int n, int SB) {
    if ((int)blockIdx.x < SB) {
        int i = blockIdx.x * 256 + threadIdx.x;
        if (i >= e + n) return;
        int d, s;
        if (i < e) { d = dst[i]; s = src[i]; }
        else       { d = i - e;  s = i - e;  }
        int p = atomicAdd(&cursor[d], 1);
        srcs[p] = s;
    } else {
        int bid2 = blockIdx.x - SB;
        int row  = bid2 * 8 + (threadIdx.x >> 5);
        int lane = threadIdx.x & 31;
        if (row >= n) return;
        float4 a = ((const float4*)(x + (size_t)row * DD))[lane];
        float4 b = ((const float4*)Wg0)[lane];
        float s  = a.x * b.x + a.y * b.y + a.z * b.z + a.w * b.w;
        #pragma unroll
        for (int o = 16; o; o >>= 1) s += __shfl_xor_sync(0xffffffffu, s, o);
        if (lane == 0) gate[row] = s + bg0[0];
    }
}

// ---------------- fused softmax-attention aggregation (warp per dst node) -----
// two-pass, 2x unrolled, fp32 gather — EXACT R13 version (benched 35us)
__global__ void __launch_bounds__(256)
edge_agg_kernel(const int* __restrict__ rowptr, const int* __restrict__ srcs,
                const float* __restrict__ g, const float* __restrict__ h,
                float* __restrict__ agg, int n) {
    int gt   = blockIdx.x * blockDim.x + threadIdx.x;
    int w    = gt >> 5;
    int lane = gt & 31;
    if (w >= n) return;
    int beg = rowptr[w];
    int end = rowptr[w + 1];

    float m = -3.4e38f, s = 0.f;
    for (int j0 = beg; j0 < end; j0 += 32) {
        int  j  = j0 + lane;
        bool ok = (j < end);
        float gi = ok ? g[srcs[j]] : -3.4e38f;
        float mn = fmaxf(m, gi);
        s = s * __expf(m - mn) + (ok ? __expf(gi - mn) : 0.f);
        m = mn;
    }
    #pragma unroll
    for (int o = 16; o; o >>= 1) {
        float om = __shfl_xor_sync(0xffffffffu, m, o);
        float os = __shfl_xor_sync(0xffffffffu, s, o);
        float mn = fmaxf(m, om);
        s = s * __expf(m - mn) + os * __expf(om - mn);
        m = mn;
    }
    float inv = 1.f / s;

    float4 acc0 = make_float4(0.f, 0.f, 0.f, 0.f);
    float4 acc1 = make_float4(0.f, 0.f, 0.f, 0.f);
    for (int j0 = beg; j0 < end; j0 += 32) {
        int  j  = j0 + lane;
        bool ok = (j < end);
        int   sj  = ok ? srcs[j] : 0;
        float wgt = ok ? __expf(g[sj] - m) * inv : 0.f;
        int cnt = min(32, end - j0);
        int jj = 0;
        for (; jj + 1 < cnt; jj += 2) {
            float w0 = __shfl_sync(0xffffffffu, wgt, jj);
            float w1 = __shfl_sync(0xffffffffu, wgt, jj + 1);
            int   s0 = __shfl_sync(0xffffffffu, sj, jj);
            int   s1 = __shfl_sync(0xffffffffu, sj, jj + 1);
            float4 v0 = ((const float4*)(h + (size_t)s0 * DD))[lane];
            float4 v1 = ((const float4*)(h + (size_t)s1 * DD))[lane];
            acc0.x = fmaf(w0, v0.x, acc0.x); acc1.x = fmaf(w1, v1.x, acc1.x);
            acc0.y = fmaf(w0, v0.y, acc0.y); acc1.y = fmaf(w1, v1.y, acc1.y);
            acc0.z = fmaf(w0, v0.z, acc0.z); acc1.z = fmaf(w1, v1.z, acc1.z);
            acc0.w = fmaf(w0, v0.w, acc0.w); acc1.w = fmaf(w1, v1.w, acc1.w);
        }
        if (jj < cnt) {
            float w0 = __shfl_sync(0xffffffffu, wgt, jj);
            int   s0 = __shfl_sync(0xffffffffu, sj, jj);
            float4 v0 = ((const float4*)(h + (size_t)s0 * DD))[lane];
            acc0.x = fmaf(w0, v0.x, acc0.x);
            acc0.y = fmaf(w0, v0.y, acc0.y);
            acc0.z = fmaf(w0, v0.z, acc0.z);
            acc0.w = fmaf(w0, v0.w, acc0.w);
        }
    }
    acc0.x += acc1.x; acc0.y += acc1.y; acc0.z += acc1.z; acc0.w += acc1.w;
    ((float4*)(agg + (size_t)w * DD))[lane] = acc0;
}

// =====================================================================
// HMMA fused layer chain (persistent, 1024 threads, 1 block/SM).
// ALGEBRAIC FUSION: Wf = Wt@W1 computed once per block via tensor-core
// prologue; bf = bt@W1 + b1. Then per 128-row tile only TWO stages:
//   S0: z = hsw(BN(A @ Wf + bf))
//   S1: h = hsw(z @ W2 + b2) -> fp32; (!LAST) gate = h . WgN + bgN
// fp16 2-product activations vs fp16-hi weights. (Benched: rel_err 1.1e-6)
// =====================================================================
#define WB        32768
#define SM_W0     0          /* Wf (computed)  */
#define SM_W1     32768      /* W1 staged (prologue only); gpp after */
#define SM_W2     65536
#define SM_B0     98304      /* hi 32KB | lo 32KB */
#define SM_B1     163840     /* hi 32KB | lo 32KB */
#define SM_CONST  229376     /* 640 floats */
#define CHAIN_SMEM 231936

template <int LAST>
__global__ void __launch_bounds__(1024)
chain2_mma(const float* __restrict__ A,
           const float* __restrict__ Wt,  const float* __restrict__ bt,
           const float* __restrict__ W1,  const float* __restrict__ b1,
           const float* __restrict__ bng, const float* __restrict__ bnb,
           const float* __restrict__ bnm, const float* __restrict__ bnv,
           const float* __restrict__ W2,  const float* __restrict__ b2,
           const float* __restrict__ WgN, const float* __restrict__ bgN,
           float* __restrict__ hout, float* __restrict__ gate, int nrows) {
    extern __shared__ char smem[];
    const uint32_t sb = smem_u32(smem);
    float* cst = (float*)(smem + SM_CONST);   // bf | scale | shift | b2 | wg
    float* gpp = (float*)(smem + SM_W1);      // gate partials (W1 dead post-prologue)
    const int tid  = threadIdx.x;
    const int wid  = tid >> 5;
    const int lane = tid & 31;
    const int mt = wid & 7;          // row block of 16 (128 rows)
    const int nb = wid >> 3;         // col block of 32
    const int g  = lane >> 2, tg = lane & 3;
    const int lq = lane >> 3, lr = lane & 7;

    // ---- stage W1, W2 (fp16 hi, [n][k] swizzled) ----
    {
        __half* s1 = (__half*)(smem + SM_W1);
        __half* s2 = (__half*)(smem + SM_W2);
        for (int i = tid; i < DD * DD; i += 1024) {
            int k = i >> 7, n = i & 127;
            int off = n * 128 + (((k >> 3) ^ (n & 7)) << 3) + (k & 7);
            s1[off] = __float2half(W1[i]);
            s2[off] = __float2half(W2[i]);
        }
    }
    // ---- constants: bf = bt@W1 + b1; BN scale/shift; b2; wg ----
    if (tid < 128) {
        float a = b1[tid];
        for (int k = 0; k < 128; k++) a = fmaf(bt[k], W1[k * 128 + tid], a);
        cst[tid] = a;
        float sv = bng[tid] * rsqrtf(bnv[tid] + 1e-5f);
        cst[128 + tid] = sv;
        cst[256 + tid] = bnb[tid] - bnm[tid] * sv;
        cst[384 + tid] = b2[tid];
        cst[512 + tid] = LAST ? 0.f : WgN[tid];
    }
    const float bgv = LAST ? 0.f : bgN[0];

    // ---- load Wt into B0 as split activations ----
    #pragma unroll
    for (int it = 0; it < 4; it++) {
        int idx = it * 1024 + tid;
        int r = idx >> 5, c4 = idx & 31;
        float4 f = ((const float4*)(Wt + (size_t)r * DD))[c4];
        uint32_t l01, l23;
        uint32_t h01 = split_f16(f.x, f.y, l01);
        uint32_t h23 = split_f16(f.z, f.w, l23);
        uint32_t off = (uint32_t)r * 256
                     + ((uint32_t)((c4 >> 1) ^ (r & 7)) << 4) + (c4 & 1) * 8;
        *(uint2*)(smem + SM_B0 + off)         = make_uint2(h01, h23);
        *(uint2*)(smem + SM_B0 + 32768 + off) = make_uint2(l01, l23);
    }
    __syncthreads();

    const int a_row = mt * 16 + lr + ((lq & 1) << 3);
    const int a_kh  = lq >> 1;
    const int b_row = nb * 32 + lr + ((lq >> 1) << 3);
    const int b_kh  = lq & 1;
    const int r0l   = mt * 16 + g;

    // ---- prologue MMA: Wf = Wt @ W1 ----
    {
        const uint32_t aRowHi = sb + SM_B0 + a_row * 256;
        const uint32_t aRowLo = sb + SM_B0 + 32768 + a_row * 256;
        const uint32_t bRow   = sb + SM_W1 + b_row * 256;
        float acc[4][4];
        #pragma unroll
        for (int i = 0; i < 4; i++) {
            acc[i][0] = 0.f; acc[i][1] = 0.f; acc[i][2] = 0.f; acc[i][3] = 0.f;
        }
        #pragma unroll
        for (int kk = 0; kk < 8; kk++) {
            uint32_t ca = (uint32_t)(((2 * kk + a_kh) ^ lr) << 4);
            uint32_t cb = (uint32_t)(((2 * kk + b_kh) ^ lr) << 4);
            uint32_t ah0, ah1, ah2, ah3, al0, al1, al2, al3;
            LDM4(ah0, ah1, ah2, ah3, aRowHi + ca);
            LDM4(al0, al1, al2, al3, aRowLo + ca);
            uint32_t bh0, bh1, bh2, bh3, bh4, bh5, bh6, bh7;
            LDM4(bh0, bh1, bh2, bh3, bRow + cb);
            LDM4(bh4, bh5, bh6, bh7, bRow + 4096 + cb);
            MMAF16(acc[0], ah0, ah1, ah2, ah3, bh0, bh1);
            MMAF16(acc[1], ah0, ah1, ah2, ah3, bh2, bh3);
            MMAF16(acc[2], ah0, ah1, ah2, ah3, bh4, bh5);
            MMAF16(acc[3], ah0, ah1, ah2, ah3, bh6, bh7);
            MMAF16(acc[0], al0, al1, al2, al3, bh0, bh1);
            MMAF16(acc[1], al0, al1, al2, al3, bh2, bh3);
            MMAF16(acc[2], al0, al1, al2, al3, bh4, bh5);
            MMAF16(acc[3], al0, al1, al2, al3, bh6, bh7);
        }
        __syncthreads();   // all prologue MMAs done (W1 reads complete)
        __half* wf = (__half*)(smem + SM_W0);
        #pragma unroll
        for (int tt = 0; tt < 4; tt++) {
            int c0 = nb * 32 + tt * 8 + 2 * tg, c1 = c0 + 1;
            int k0 = r0l, k1 = r0l + 8;
            wf[c0 * 128 + (((k0 >> 3) ^ (c0 & 7)) << 3) + (k0 & 7)] = __float2half(acc[tt][0]);
            wf[c1 * 128 + (((k0 >> 3) ^ (c1 & 7)) << 3) + (k0 & 7)] = __float2half(acc[tt][1]);
            wf[c0 * 128 + (((k1 >> 3) ^ (c0 & 7)) << 3) + (k1 & 7)] = __float2half(acc[tt][2]);
            wf[c1 * 128 + (((k1 >> 3) ^ (c1 & 7)) << 3) + (k1 & 7)] = __float2half(acc[tt][3]);
        }
    }
    __syncthreads();   // Wf ready; B0 free

    const int ntiles = (nrows + 127) >> 7;
    int t = blockIdx.x;
    if (t < ntiles) {   // initial A tile -> B0
        #pragma unroll
        for (int it = 0; it < 4; it++) {
            int idx = it * 1024 + tid;
            int r = idx >> 5, c4 = idx & 31;
            int grow = t * 128 + r;
            float4 f = make_float4(0.f, 0.f, 0.f, 0.f);
            if (grow < nrows) f = ((const float4*)(A + (size_t)grow * DD))[c4];
            uint32_t l01, l23;
            uint32_t h01 = split_f16(f.x, f.y, l01);
            uint32_t h23 = split_f16(f.z, f.w, l23);
            uint32_t off = (uint32_t)r * 256
                         + ((uint32_t)((c4 >> 1) ^ (r & 7)) << 4) + (c4 & 1) * 8;
            *(uint2*)(smem + SM_B0 + off)         = make_uint2(h01, h23);
            *(uint2*)(smem + SM_B0 + 32768 + off) = make_uint2(l01, l23);
        }
    }
    __syncthreads();

    for (; t < ntiles; t += gridDim.x) {
        // ===== stage S0: z = hsw(BN(A @ Wf + bf)) -> B1 =====
        {
            const uint32_t aRowHi = sb + SM_B0 + a_row * 256;
            const uint32_t aRowLo = sb + SM_B0 + 32768 + a_row * 256;
            const uint32_t bRow   = sb + SM_W0 + b_row * 256;
            float acc[4][4];
            #pragma unroll
            for (int i = 0; i < 4; i++) {
                acc[i][0] = 0.f; acc[i][1] = 0.f; acc[i][2] = 0.f; acc[i][3] = 0.f;
            }
            #pragma unroll
            for (int kk = 0; kk < 8; kk++) {
                uint32_t ca = (uint32_t)(((2 * kk + a_kh) ^ lr) << 4);
                uint32_t cb = (uint32_t)(((2 * kk + b_kh) ^ lr) << 4);
                uint32_t ah0, ah1, ah2, ah3, al0, al1, al2, al3;
                LDM4(ah0, ah1, ah2, ah3, aRowHi + ca);
                LDM4(al0, al1, al2, al3, aRowLo + ca);
                uint32_t bh0, bh1, bh2, bh3, bh4, bh5, bh6, bh7;
                LDM4(bh0, bh1, bh2, bh3, bRow + cb);
                LDM4(bh4, bh5, bh6, bh7, bRow + 4096 + cb);
                MMAF16(acc[0], ah0, ah1, ah2, ah3, bh0, bh1);
                MMAF16(acc[1], ah0, ah1, ah2, ah3, bh2, bh3);
                MMAF16(acc[2], ah0, ah1, ah2, ah3, bh4, bh5);
                MMAF16(acc[3], ah0, ah1, ah2, ah3, bh6, bh7);
                MMAF16(acc[0], al0, al1, al2, al3, bh0, bh1);
                MMAF16(acc[1], al0, al1, al2, al3, bh2, bh3);
                MMAF16(acc[2], al0, al1, al2, al3, bh4, bh5);
                MMAF16(acc[3], al0, al1, al2, al3, bh6, bh7);
            }
            #pragma unroll
            for (int tt = 0; tt < 4; tt++) {
                int ct = nb * 32 + tt * 8;
                int c0 = ct + 2 * tg, c1 = c0 + 1;
                float v0 = hsw((acc[tt][0] + cst[c0]) * cst[128 + c0] + cst[256 + c0]);
                float v1 = hsw((acc[tt][1] + cst[c1]) * cst[128 + c1] + cst[256 + c1]);
                float v2 = hsw((acc[tt][2] + cst[c0]) * cst[128 + c0] + cst[256 + c0]);
                float v3 = hsw((acc[tt][3] + cst[c1]) * cst[128 + c1] + cst[256 + c1]);
                uint32_t lo01, lo23;
                uint32_t h01 = split_f16(v0, v1, lo01);
                uint32_t h23 = split_f16(v2, v3, lo23);
                uint32_t chunk = (uint32_t)(((ct >> 3) ^ (r0l & 7)) << 4) + 4 * tg;
                uint32_t off0 = (uint32_t)r0l * 256 + chunk;
                uint32_t off1 = (uint32_t)(r0l + 8) * 256 + chunk;
                *(uint32_t*)(smem + SM_B1 + off0)         = h01;
                *(uint32_t*)(smem + SM_B1 + off1)         = h23;
                *(uint32_t*)(smem + SM_B1 + 32768 + off0) = lo01;
                *(uint32_t*)(smem + SM_B1 + 32768 + off1) = lo23;
            }
        }
        __syncthreads();   // (b) B1 published; B0 fully dead

        // ===== stage S1: h = hsw(z @ W2 + b2); prefetch next A into B0 =====
        {
            const int tn = t + gridDim.x;
            float4 pf[4];
            if (tn < ntiles) {
                #pragma unroll
                for (int it = 0; it < 4; it++) {
                    int idx = it * 1024 + tid;
                    int r = idx >> 5, c4 = idx & 31;
                    int grow = tn * 128 + r;
                    pf[it] = (grow < nrows) ? ((const float4*)(A + (size_t)grow * DD))[c4]
                                            : make_float4(0.f, 0.f, 0.f, 0.f);
                }
            }
            const uint32_t aRowHi = sb + SM_B1 + a_row * 256;
            const uint32_t aRowLo = sb + SM_B1 + 32768 + a_row * 256;
            const uint32_t bRow   = sb + SM_W2 + b_row * 256;
            float acc[4][4];
            #pragma unroll
            for (int i = 0; i < 4; i++) {
                acc[i][0] = 0.f; acc[i][1] = 0.f; acc[i][2] = 0.f; acc[i][3] = 0.f;
            }
            #pragma unroll
            for (int kk = 0; kk < 8; kk++) {
                uint32_t ca = (uint32_t)(((2 * kk + a_kh) ^ lr) << 4);
                uint32_t cb = (uint32_t)(((2 * kk + b_kh) ^ lr) << 4);
                uint32_t ah0, ah1, ah2, ah3, al0, al1, al2, al3;
                LDM4(ah0, ah1, ah2, ah3, aRowHi + ca);
                LDM4(al0, al1, al2, al3, aRowLo + ca);
                uint32_t bh0, bh1, bh2, bh3, bh4, bh5, bh6, bh7;
                LDM4(bh0, bh1, bh2, bh3, bRow + cb);
                LDM4(bh4, bh5, bh6, bh7, bRow + 4096 + cb);
                MMAF16(acc[0], ah0, ah1, ah2, ah3, bh0, bh1);
                MMAF16(acc[1], ah0, ah1, ah2, ah3, bh2, bh3);
                MMAF16(acc[2], ah0, ah1, ah2, ah3, bh4, bh5);
                MMAF16(acc[3], ah0, ah1, ah2, ah3, bh6, bh7);
                MMAF16(acc[0], al0, al1, al2, al3, bh0, bh1);
                MMAF16(acc[1], al0, al1, al2, al3, bh2, bh3);
                MMAF16(acc[2], al0, al1, al2, al3, bh4, bh5);
                MMAF16(acc[3], al0, al1, al2, al3, bh6, bh7);
            }
            if (tn < ntiles) {   // store prefetched A into B0 (dead since sync b)
                #pragma unroll
                for (int it = 0; it < 4; it++) {
                    int idx = it * 1024 + tid;
                    int r = idx >> 5, c4 = idx & 31;
                    float4 f = pf[it];
                    uint32_t l01, l23;
                    uint32_t h01 = split_f16(f.x, f.y, l01);
                    uint32_t h23 = split_f16(f.z, f.w, l23);
                    uint32_t off = (uint32_t)r * 256
                                 + ((uint32_t)((c4 >> 1) ^ (r & 7)) << 4) + (c4 & 1) * 8;
                    *(uint2*)(smem + SM_B0 + off)         = make_uint2(h01, h23);
                    *(uint2*)(smem + SM_B0 + 32768 + off) = make_uint2(l01, l23);
                }
            }
            int gr0 = t * 128 + r0l, gr1 = gr0 + 8;
            float p0 = 0.f, p1 = 0.f;
            #pragma unroll
            for (int tt = 0; tt < 4; tt++) {
                int ct = nb * 32 + tt * 8;
                int c0 = ct + 2 * tg, c1 = c0 + 1;
                float q0 = hsw(acc[tt][0] + cst[384 + c0]);
                float q1 = hsw(acc[tt][1] + cst[384 + c1]);
                float q2 = hsw(acc[tt][2] + cst[384 + c0]);
                float q3 = hsw(acc[tt][3] + cst[384 + c1]);
                if (!LAST) {
                    p0 = fmaf(q0, cst[512 + c0], fmaf(q1, cst[512 + c1], p0));
                    p1 = fmaf(q2, cst[512 + c0], fmaf(q3, cst[512 + c1], p1));
                }
                if (gr0 < nrows)
                    *(float2*)(hout + (size_t)gr0 * DD + c0) = make_float2(q0, q1);
                if (gr1 < nrows)
                    *(float2*)(hout + (size_t)gr1 * DD + c0) = make_float2(q2, q3);
            }
            if (!LAST) {
                p0 += __shfl_xor_sync(0xffffffffu, p0, 1);
                p0 += __shfl_xor_sync(0xffffffffu, p0, 2);
                p1 += __shfl_xor_sync(0xffffffffu, p1, 1);
                p1 += __shfl_xor_sync(0xffffffffu, p1, 2);
                if (tg == 0) {
                    gpp[r0l * 4 + nb]       = p0;
                    gpp[(r0l + 8) * 4 + nb] = p1;
                }
            }
        }
        __syncthreads();   // (c) B1 reads done; B0 next-A + gpp published

        if (!LAST) {
            if (tid < 128) {
                int gr = t * 128 + tid;
                if (gr < nrows)
                    gate[gr] = gpp[tid * 4] + gpp[tid * 4 + 1]
                             + gpp[tid * 4 + 2] + gpp[tid * 4 + 3] + bgv;
            }
        }
    }
}

// =====================================================================
// Head (HMMA): z = hsw(h@Wp1+bp1) via fp16 2-product MMA (h fp32 input);
// logits = z@Wp2+bp2 (packed FFMA2); log_softmax. 512 thr, 128-row tiles.
// =====================================================================
#define HD_WP1  0        /* 32768 */
#define HD_AHI  32768    /* 32768 */
#define HD_ALO  65536    /* 32768 */
#define HD_Z    98304    /* 128*132*4 = 67584 */
#define HD_WSH  165888   /* 20480 */
#define HEAD_SMEM 186368

__global__ void __launch_bounds__(512)
head_hmma(const float* __restrict__ h, const float* __restrict__ Wp1,
          const float* __restrict__ bp1, const float* __restrict__ Wp2,
          const float* __restrict__ bp2, float* __restrict__ out, int n) {
    extern __shared__ char smem[];
    const uint32_t sb = smem_u32(smem);
    float* zf = (float*)(smem + HD_Z);
    unsigned long long* wsh = (unsigned long long*)(smem + HD_WSH);
    const int tid  = threadIdx.x;
    const int wid  = tid >> 5;
    const int lane = tid & 31;
    const int mt = wid & 7;
    const int nb = wid >> 3;
    const int g  = lane >> 2, tg = lane & 3;
    const int lq = lane >> 3, lr = lane & 7;
    const int r0 = blockIdx.x * 128;

    {
        __half* hs = (__half*)(smem + HD_WP1);
        for (int i = tid; i < DD * DD; i += 512) {
            int k = i >> 7, nn = i & 127;
            int off = nn * 128 + (((k >> 3) ^ (nn & 7)) << 3) + (k & 7);
            hs[off] = __float2half(Wp1[i]);
        }
    }
    for (int idx = tid; idx < DD * 20; idx += 512) {
        int k = idx / 20, j = idx % 20;
        wsh[idx] = pack2(Wp2[k * CC + 2 * j], Wp2[k * CC + 2 * j + 1]);
    }
    #pragma unroll
    for (int it = 0; it < 8; it++) {
        int idx = it * 512 + tid;
        int r = idx >> 5, c4 = idx & 31;
        int grow = r0 + r;
        float4 f = make_float4(0.f, 0.f, 0.f, 0.f);
        if (grow < n) f = ((const float4*)(h + (size_t)grow * DD))[c4];
        uint32_t l01, l23;
        uint32_t h01 = split_f16(f.x, f.y, l01);
        uint32_t h23 = split_f16(f.z, f.w, l23);
        uint32_t off = (uint32_t)r * 256
                     + ((uint32_t)((c4 >> 1) ^ (r & 7)) << 4) + (c4 & 1) * 8;
        *(uint2*)(smem + HD_AHI + off) = make_uint2(h01, h23);
        *(uint2*)(smem + HD_ALO + off) = make_uint2(l01, l23);
    }
    __syncthreads();

    const int a_row = mt * 16 + lr + ((lq & 1) << 3);
    const int a_kh  = lq >> 1;
    const int b_kh  = lq & 1;
    const uint32_t aRowHi = sb + HD_AHI + a_row * 256;
    const uint32_t aRowLo = sb + HD_ALO + a_row * 256;
    const int brb0 = (nb * 2 + 0) * 32 + lr + ((lq >> 1) << 3);
    const int brb1 = (nb * 2 + 1) * 32 + lr + ((lq >> 1) << 3);
    const uint32_t bRow0 = sb + HD_WP1 + brb0 * 256;
    const uint32_t bRow1 = sb + HD_WP1 + brb1 * 256;
    const int r0l = mt * 16 + g;

    float acc[2][4][4];
    #pragma unroll
    for (int h2 = 0; h2 < 2; h2++)
        #pragma unroll
        for (int i = 0; i < 4; i++) {
            acc[h2][i][0] = 0.f; acc[h2][i][1] = 0.f;
            acc[h2][i][2] = 0.f; acc[h2][i][3] = 0.f;
        }
    #pragma unroll
    for (int kk = 0; kk < 8; kk++) {
        uint32_t ca = (uint32_t)(((2 * kk + a_kh) ^ lr) << 4);
        uint32_t cb = (uint32_t)(((2 * kk + b_kh) ^ lr) << 4);
        uint32_t ah0, ah1, ah2, ah3, al0, al1, al2, al3;
        LDM4(ah0, ah1, ah2, ah3, aRowHi + ca);
        LDM4(al0, al1, al2, al3, aRowLo + ca);
        uint32_t b00, b01, b02, b03, b04, b05, b06, b07;
        LDM4(b00, b01, b02, b03, bRow0 + cb);
        LDM4(b04, b05, b06, b07, bRow0 + 4096 + cb);
        MMAF16(acc[0][0], ah0, ah1, ah2, ah3, b00, b01);
        MMAF16(acc[0][1], ah0, ah1, ah2, ah3, b02, b03);
        MMAF16(acc[0][2], ah0, ah1, ah2, ah3, b04, b05);
        MMAF16(acc[0][3], ah0, ah1, ah2, ah3, b06, b07);
        MMAF16(acc[0][0], al0, al1, al2, al3, b00, b01);
        MMAF16(acc[0][1], al0, al1, al2, al3, b02, b03);
        MMAF16(acc[0][2], al0, al1, al2, al3, b04, b05);
        MMAF16(acc[0][3], al0, al1, al2, al3, b06, b07);
        uint32_t b10, b11, b12, b13, b14, b15, b16, b17;
        LDM4(b10, b11, b12, b13, bRow1 + cb);
        LDM4(b14, b15, b16, b17, bRow1 + 4096 + cb);
        MMAF16(acc[1][0], ah0, ah1, ah2, ah3, b10, b11);
        MMAF16(acc[1][1], ah0, ah1, ah2, ah3, b12, b13);
        MMAF16(acc[1][2], ah0, ah1, ah2, ah3, b14, b15);
        MMAF16(acc[1][3], ah0, ah1, ah2, ah3, b16, b17);
        MMAF16(acc[1][0], al0, al1, al2, al3, b10, b11);
        MMAF16(acc[1][1], al0, al1, al2, al3, b12, b13);
        MMAF16(acc[1][2], al0, al1, al2, al3, b14, b15);
        MMAF16(acc[1][3], al0, al1, al2, al3, b16, b17);
    }
    #pragma unroll
    for (int h2 = 0; h2 < 2; h2++) {
        #pragma unroll
        for (int tt = 0; tt < 4; tt++) {
            int c0 = (nb * 2 + h2) * 32 + tt * 8 + 2 * tg;
            float bb0 = bp1[c0], bb1 = bp1[c0 + 1];
            float q0 = hsw(acc[h2][tt][0] + bb0);
            float q1 = hsw(acc[h2][tt][1] + bb1);
            float q2 = hsw(acc[h2][tt][2] + bb0);
            float q3 = hsw(acc[h2][tt][3] + bb1);
            *(float2*)(zf + r0l * 132 + c0)       = make_float2(q0, q1);
            *(float2*)(zf + (r0l + 8) * 132 + c0) = make_float2(q2, q3);
        }
    }
    __syncthreads();

    const int rl = tid >> 2;
    const int q  = tid & 3;
    unsigned long long acc2[5];
    #pragma unroll
    for (int j = 0; j < 5; j++)
        acc2[j] = pack2(bp2[q * 10 + 2 * j], bp2[q * 10 + 2 * j + 1]);
    const float* ar = zf + rl * 132;
    #pragma unroll 4
    for (int k = 0; k < DD; k++) {
        float a = ar[k];
        unsigned long long ad = pack2(a, a);
        const unsigned long long* wr = wsh + k * 20 + q * 5;
        #pragma unroll
        for (int j = 0; j < 5; j++) acc2[j] = ffma2(ad, wr[j], acc2[j]);
    }
    float vals[10];
    #pragma unroll
    for (int j = 0; j < 5; j++) {
        float2 p = unpack2(acc2[j]);
        vals[2 * j] = p.x;
        vals[2 * j + 1] = p.y;
    }
    float mx = vals[0];
    #pragma unroll
    for (int c = 1; c < 10; c++) mx = fmaxf(mx, vals[c]);
    mx = fmaxf(mx, __shfl_xor_sync(0xffffffffu, mx, 1));
    mx = fmaxf(mx, __shfl_xor_sync(0xffffffffu, mx, 2));
    float s = 0.f;
    #pragma unroll
    for (int c = 0; c < 10; c++) s += __expf(vals[c] - mx);
    s += __shfl_xor_sync(0xffffffffu, s, 1);
    s += __shfl_xor_sync(0xffffffffu, s, 2);
    float lse = mx + logf(s);
    int gr = r0 + rl;
    if (gr < n) {
        #pragma unroll
        for (int c = 0; c < 10; c++) out[(size_t)gr * CC + q * 10 + c] = vals[c] - lse;
    }
}

// ---------------- launch orchestration ----------------
extern "C" void kernel_launch(void* const* d_in, const int* in_sizes, int n_in,
                              void* d_out, int out_size) {
    const float* x   = (const float*)d_in[0];
    const int*   src = (const int*)d_in[1];
    const int*   dst = (const int*)d_in[2];
    const float* Wg  = (const float*)d_in[3];
    const float* bg  = (const float*)d_in[4];
    const float* Wt  = (const float*)d_in[5];
    const float* bt  = (const float*)d_in[6];
    const float* W1  = (const float*)d_in[7];
    const float* b1  = (const float*)d_in[8];
    const float* bng = (const float*)d_in[9];
    const float* bnb = (const float*)d_in[10];
    const float* bnm = (const float*)d_in[11];
    const float* bnv = (const float*)d_in[12];
    const float* W2  = (const float*)d_in[13];
    const float* b2  = (const float*)d_in[14];
    const float* Wp1 = (const float*)d_in[15];
    const float* bp1 = (const float*)d_in[16];
    const float* Wp2 = (const float*)d_in[17];
    const float* bp2 = (const float*)d_in[18];
    float* out = (float*)d_out;

    const int n = in_sizes[0] / DD;
    const int e = in_sizes[1];

    float *ph, *pagg, *pg;
    int *prow, *pcur, *psrc;
    cudaGetSymbolAddress((void**)&ph,   g_h);
    cudaGetSymbolAddress((void**)&pagg, g_agg);
    cudaGetSymbolAddress((void**)&pg,   g_gate);
    cudaGetSymbolAddress((void**)&prow, g_rowptr);
    cudaGetSymbolAddress((void**)&pcur, g_cursor);
    cudaGetSymbolAddress((void**)&psrc, g_srcs);

    cudaFuncSetAttribute(chain2_mma<0>, cudaFuncAttributeMaxDynamicSharedMemorySize, CHAIN_SMEM);
    cudaFuncSetAttribute(chain2_mma<1>, cudaFuncAttributeMaxDynamicSharedMemorySize, CHAIN_SMEM);
    cudaFuncSetAttribute(head_hmma, cudaFuncAttributeMaxDynamicSharedMemorySize, HEAD_SMEM);

    // CSR build + layer-0 gate
    cudaMemsetAsync(pcur, 0, n * sizeof(int));
    count_ext_kernel<<<(e + n + 255) / 256, 256>>>(dst, pcur, e, n);
    scan_kernel<<<1, 1024>>>(pcur, prow, n);
    const int SB = (e + n + 255) / 256;
    const int GB = (n + 7) / 8;
    scatter_gate_kernel<<<SB + GB, 256>>>(src, dst, pcur, psrc,
                                          x, Wg, bg, pg, e, n, SB);

    const int wblocks = (n * 32 + 255) / 256;
    const int PERS = 148;

    for (int i = 0; i < LL; i++) {
        const float* hin = (i == 0) ? x : ph;
        edge_agg_kernel<<<wblocks, 256>>>(prow, psrc, pg, hin, pagg, n);
        if (i < LL - 1) {
            chain2_mma<0><<<PERS, 1024, CHAIN_SMEM>>>(
                pagg,
                Wt + (size_t)i * DD * DD, bt + (size_t)i * DD,
                W1 + (size_t)i * DD * DD, b1 + (size_t)i * DD,
                bng + (size_t)i * DD, bnb + (size_t)i * DD,
                bnm + (size_t)i * DD, bnv + (size_t)i * DD,
                W2 + (size_t)i * DD * DD, b2 + (size_t)i * DD,
                Wg + (size_t)(i + 1) * DD, bg + (i + 1),
                ph, pg, n);
        } else {
            chain2_mma<1><<<PERS, 1024, CHAIN_SMEM>>>(
                pagg,
                Wt + (size_t)i * DD * DD, bt + (size_t)i * DD,
                W1 + (size_t)i * DD * DD, b1 + (size_t)i * DD,
                bng + (size_t)i * DD, bnb + (size_t)i * DD,
                bnm + (size_t)i * DD, bnv + (size_t)i * DD,
                W2 + (size_t)i * DD * DD, b2 + (size_t)i * DD,
                nullptr, nullptr,
                ph, nullptr, n);
        }
    }
    head_hmma<<<(n + 127) / 128, 512, HEAD_SMEM>>>(ph, Wp1, bp1, Wp2, bp2, out, n);
}